// round 2
// baseline (speedup 1.0000x reference)
#include <cuda_runtime.h>
#include <cstdint>

// QSVT <Z> reduced to closed form:
//   x = clamp(x,-1,1), u = x^2, s = sqrt(1-u)
//   <Z>(x) = cos(x)*h(u) + s*x*sin(x)*g(u)
// where h (deg<=7 in u) and g (deg<=6 in u) are fixed polynomials of the
// phases phi[0..6] (phi[7] and theta are diagonal phases -> dead for <Z>).
//
// Derivation: Bloch dynamics. M = Refl * prod(Rot_j * Refl), Refl entries are
// even-poly(u) on the (x,z)|(y) diagonal blocks and s*x*poly(u) off-diagonal;
// rotations (constant) preserve this grading, so the bottom row of M is
// (s*x*o20(u), s*x*o21(u), e22(u)). With initial state
// (cos2phi0*sinx, -sin2phi0*sinx, cosx) this gives the closed form above.
//
// Setup kernel: evaluates the exact double-precision recurrence at the 8
// Chebyshev-Gauss nodes y_j=cos((j+.5)pi/8) (two linear-independent initial
// states to separate h and g), then an 8-point DCT yields the Chebyshev
// coefficients in y = 2u-1. Exact (degrees <= 7). Main kernel: packed-f32x2
// Clenshaw, numerically stable (coeffs O(1)).

typedef unsigned long long u64;

__device__ u64 g_pk[16];  // [0..7] = h cheb coeffs (dup-packed), [8..14] = g, [15] spare

// ------------------------- setup (runs in-graph, tiny) -------------------------
__global__ void qsvt_setup(const float* __restrict__ phi) {
    __shared__ double hv[8], gv[8];
    const double PI = 3.14159265358979323846;
    int t = threadIdx.x;
    if (t < 8) {
        double th = (t + 0.5) * (PI / 8.0);
        double y = cos(th);
        double u = 0.5 * (y + 1.0);
        double x = sqrt(u);
        double s = sqrt(1.0 - u);
        double A = 1.0 - 2.0 * u;
        double B = 2.0 * s * x;
        double C[7], SP[7], SN[7];
#pragma unroll
        for (int k = 0; k < 7; k++) {
            double sg = (k & 1) ? -1.0 : 1.0;
            double ss, cc;
            sincos(2.0 * (double)phi[k], &ss, &cc);
            C[k] = cc; SP[k] = sg * ss; SN[k] = -sg * ss;
        }
        for (int m = 0; m < 2; m++) {
            double rx, w, rz;
            if (m == 0) { rx = 0.0; w = 0.0; rz = 1.0; }      // -> e22 = h
            else        { rx = C[0]; w = SN[0]; rz = 0.0; }   // -> s*x*g
            for (int j = 1; j <= 7; j++) {
                double nrx = A * rx + B * rz;
                double nrz = B * rx - A * rz;
                rx = nrx; rz = nrz;
                if (j < 7) {
                    double rx2 = C[j] * rx + SP[j] * w;
                    w = C[j] * w + SN[j] * rx;
                    rx = rx2;
                }
            }
            if (m == 0) hv[t] = rz;
            else        gv[t] = rz / (s * x);
        }
    }
    __syncthreads();
    if (t < 16) {
        int k = t & 7;
        const double* src = (t < 8) ? hv : gv;
        double acc = 0.0;
#pragma unroll
        for (int j = 0; j < 8; j++)
            acc += src[j] * cos((double)k * ((double)j + 0.5) * (PI / 8.0));
        acc *= ((k == 0) ? 1.0 : 2.0) / 8.0;
        float f = (float)acc;
        u64 pkv = ((u64)__float_as_uint(f) << 32) | (u64)__float_as_uint(f);
        g_pk[(t < 8 ? 0 : 8) + k] = pkv;
    }
    if (t == 16) g_pk[15] = 0ULL;
}

// ---------------------- packed f32x2 helpers ----------------------
__device__ __forceinline__ u64 pk2(float lo, float hi) {
    u64 r; asm("mov.b64 %0, {%1, %2};" : "=l"(r) : "f"(lo), "f"(hi)); return r;
}
__device__ __forceinline__ void unpk2(u64 v, float& lo, float& hi) {
    asm("mov.b64 {%0, %1}, %2;" : "=f"(lo), "=f"(hi) : "l"(v));
}
__device__ __forceinline__ u64 fma2(u64 a, u64 b, u64 c) {
    u64 d; asm("fma.rn.f32x2 %0, %1, %2, %3;" : "=l"(d) : "l"(a), "l"(b), "l"(c)); return d;
}
__device__ __forceinline__ u64 mul2(u64 a, u64 b) {
    u64 d; asm("mul.rn.f32x2 %0, %1, %2;" : "=l"(d) : "l"(a), "l"(b)); return d;
}
// ---------------------- scalar MUFU ----------------------
__device__ __forceinline__ float aprx_sqrt(float x) {
    float r; asm("sqrt.approx.f32 %0, %1;" : "=f"(r) : "f"(x)); return r;
}
__device__ __forceinline__ float aprx_sin(float x) {
    float r; asm("sin.approx.f32 %0, %1;" : "=f"(r) : "f"(x)); return r;
}
__device__ __forceinline__ float aprx_cos(float x) {
    float r; asm("cos.approx.f32 %0, %1;" : "=f"(r) : "f"(x)); return r;
}

// Two elements packed; returns packed <Z>.
__device__ __forceinline__ u64 qsvt_pair(float xa, float xb,
                                         const u64* __restrict__ K,
                                         u64 FOUR, u64 NEG2, u64 TWO, u64 NEG1) {
    xa = fminf(fmaxf(xa, -1.0f), 1.0f);
    xb = fminf(fmaxf(xb, -1.0f), 1.0f);
    float ta = fmaxf(fmaf(-xa, xa, 1.0f), 0.0f);
    float tb = fmaxf(fmaf(-xb, xb, 1.0f), 0.0f);
    float sa = aprx_sqrt(ta), sb = aprx_sqrt(tb);
    float sina = aprx_sin(xa), cosa = aprx_cos(xa);
    float sinb = aprx_sin(xb), cosb = aprx_cos(xb);

    u64 X = pk2(xa, xb);
    u64 U = mul2(X, X);
    u64 TWOY = fma2(U, FOUR, NEG2);             // 2*(2u-1)
    u64 Y    = fma2(U, TWO,  NEG1);             // 2u-1
    u64 M1 = mul2(mul2(X, pk2(sa, sb)), pk2(sina, sinb));  // s*x*sin(x)
    u64 CS = pk2(cosa, cosb);

    // sub2(a,b) = a - b via fma(b, -1, a)
    // Clenshaw for h: coeffs K[0..7] (deg 7 in y)
    u64 b1 = K[7], b2, t;
    t = fma2(TWOY, b1, K[6]);                     b2 = b1; b1 = t;
    t = fma2(b2, NEG1, fma2(TWOY, b1, K[5]));     b2 = b1; b1 = t;
    t = fma2(b2, NEG1, fma2(TWOY, b1, K[4]));     b2 = b1; b1 = t;
    t = fma2(b2, NEG1, fma2(TWOY, b1, K[3]));     b2 = b1; b1 = t;
    t = fma2(b2, NEG1, fma2(TWOY, b1, K[2]));     b2 = b1; b1 = t;
    t = fma2(b2, NEG1, fma2(TWOY, b1, K[1]));     b2 = b1; b1 = t;
    u64 H = fma2(b2, NEG1, fma2(Y, b1, K[0]));

    // Clenshaw for g: coeffs K[8..14] (deg 6 in y)
    b1 = K[14];
    t = fma2(TWOY, b1, K[13]);                    b2 = b1; b1 = t;
    t = fma2(b2, NEG1, fma2(TWOY, b1, K[12]));    b2 = b1; b1 = t;
    t = fma2(b2, NEG1, fma2(TWOY, b1, K[11]));    b2 = b1; b1 = t;
    t = fma2(b2, NEG1, fma2(TWOY, b1, K[10]));    b2 = b1; b1 = t;
    t = fma2(b2, NEG1, fma2(TWOY, b1, K[9]));     b2 = b1; b1 = t;
    u64 G = fma2(b2, NEG1, fma2(Y, b1, K[8]));

    return fma2(M1, G, mul2(CS, H));              // cos*h + sxsin*g
}

__global__ void __launch_bounds__(256) qsvt_main(const float* __restrict__ xin,
                                                 float* __restrict__ out,
                                                 int n) {
    u64 K[16];
    {
        const ulonglong2* p = reinterpret_cast<const ulonglong2*>(g_pk);
#pragma unroll
        for (int i = 0; i < 8; i++) { ulonglong2 v = p[i]; K[2 * i] = v.x; K[2 * i + 1] = v.y; }
    }
    const u64 FOUR = pk2(4.0f, 4.0f);
    const u64 NEG2 = pk2(-2.0f, -2.0f);
    const u64 TWO  = pk2(2.0f, 2.0f);
    const u64 NEG1 = pk2(-1.0f, -1.0f);

    long long tid  = (long long)blockIdx.x * blockDim.x + threadIdx.x;
    long long base = tid * 8;
    if (base >= n) return;

    if (base + 8 <= n) {
        float4 a = *reinterpret_cast<const float4*>(xin + base);
        float4 b = *reinterpret_cast<const float4*>(xin + base + 4);

        u64 r01 = qsvt_pair(a.x, a.y, K, FOUR, NEG2, TWO, NEG1);
        u64 r23 = qsvt_pair(a.z, a.w, K, FOUR, NEG2, TWO, NEG1);
        u64 r45 = qsvt_pair(b.x, b.y, K, FOUR, NEG2, TWO, NEG1);
        u64 r67 = qsvt_pair(b.z, b.w, K, FOUR, NEG2, TWO, NEG1);

        float4 o1, o2;
        unpk2(r01, o1.x, o1.y);
        unpk2(r23, o1.z, o1.w);
        unpk2(r45, o2.x, o2.y);
        unpk2(r67, o2.z, o2.w);
        *reinterpret_cast<float4*>(out + base)     = o1;
        *reinterpret_cast<float4*>(out + base + 4) = o2;
    } else {
        for (long long i = base; i < n; i++) {
            u64 r = qsvt_pair(xin[i], 0.0f, K, FOUR, NEG2, TWO, NEG1);
            float lo, hi;
            unpk2(r, lo, hi);
            out[i] = lo;
        }
    }
}

extern "C" void kernel_launch(void* const* d_in, const int* in_sizes, int n_in,
                              void* d_out, int out_size) {
    const float* x   = (const float*)d_in[0];
    // d_in[1] = theta: dead (diagonal phase, does not affect <Z>)
    const float* phi = (const float*)d_in[2];
    float* out = (float*)d_out;

    qsvt_setup<<<1, 32>>>(phi);

    int n = out_size;
    long long threads = ((long long)n + 7) / 8;
    int blocks = (int)((threads + 255) / 256);
    qsvt_main<<<blocks, 256>>>(x, out, n);
}

// round 3
// speedup vs baseline: 1.3279x; 1.3279x over previous
#include <cuda_runtime.h>
#include <cstdint>

// QSVT <Z> closed form:
//   x = clamp(x,-1,1), u = x^2, s = sqrt(1-u)
//   <Z>(x) = cos(x)*h(u) + s*x*sin(x)*g(u),  deg_u h <= 7, deg_u g <= 6.
// (phi[7] and theta are diagonal phases -> dead for <Z>.)
//
// Setup: evaluate the exact Bloch recurrence at the 8 Chebyshev-Gauss nodes
// in y = 2u-1 (double arithmetic, but NO double transcendentals: node/DCT
// cosines come from a compile-time table, phase sincos is fp32), 8-pt DCT ->
// Chebyshev coeffs, exact integer T-matrix -> monomial-in-y coeffs (double),
// round to f32 dup-packed. Main kernel: packed-f32x2 Horner in y (stable:
// monomial-in-y coeffs are O(10..100)).

typedef unsigned long long u64;

__device__ u64 g_pk[16];  // [0..7] = h monomial coeffs (y-basis, dup-packed), [8..14] = g

// cos(m*pi/16), m = 0..16 (compile-time doubles; no runtime double trig)
__device__ __constant__ double c_cos16[17] = {
    1.0,
    0.98078528040323044913,  0.92387953251128675613,
    0.83146961230254523708,  0.70710678118654752440,
    0.55557023301960222474,  0.38268343236508977173,
    0.19509032201612826785,  0.0,
   -0.19509032201612826785, -0.38268343236508977173,
   -0.55557023301960222474, -0.70710678118654752440,
   -0.83146961230254523708, -0.92387953251128675613,
   -0.98078528040323044913, -1.0
};

// T_k(y) monomial coefficients, k=0..7 (integers, exact)
__device__ __constant__ double c_T[8][8] = {
    { 1,  0,  0,  0,   0,    0,  0,  0},
    { 0,  1,  0,  0,   0,    0,  0,  0},
    {-1,  0,  2,  0,   0,    0,  0,  0},
    { 0, -3,  0,  4,   0,    0,  0,  0},
    { 1,  0, -8,  0,   8,    0,  0,  0},
    { 0,  5,  0,-20,   0,   16,  0,  0},
    {-1,  0, 18,  0, -48,    0, 32,  0},
    { 0, -7,  0, 56,   0, -112,  0, 64}
};

__device__ __forceinline__ double cos16(int m) {
    m &= 31;
    if (m > 16) m = 32 - m;
    return c_cos16[m];
}

// ------------------------- setup (tiny, one warp) -------------------------
__global__ void qsvt_setup(const float* __restrict__ phi) {
    __shared__ double hv[8], gv[8];        // node values
    __shared__ double hc[8], gc[8];        // chebyshev coeffs
    int t = threadIdx.x;

    // rotation constants from fp32 trig (error ~1e-7, benign)
    double C[7], SP[7], SN[7];
#pragma unroll
    for (int k = 0; k < 7; k++) {
        float ss, cc;
        sincosf(2.0f * phi[k], &ss, &cc);
        double sg = (k & 1) ? -1.0 : 1.0;
        C[k] = (double)cc; SP[k] = sg * (double)ss; SN[k] = -sg * (double)ss;
    }

    if (t < 8) {
        double y = cos16(2 * t + 1);          // Chebyshev-Gauss node
        double u = 0.5 * (y + 1.0);
        double x = sqrt(u);
        double s = sqrt(1.0 - u);
        double A = 1.0 - 2.0 * u;
        double B = 2.0 * s * x;
        for (int m = 0; m < 2; m++) {
            double rx, w, rz;
            if (m == 0) { rx = 0.0; w = 0.0; rz = 1.0; }    // -> h
            else        { rx = C[0]; w = SN[0]; rz = 0.0; } // -> s*x*g
            for (int j = 1; j <= 7; j++) {
                double nrx = A * rx + B * rz;
                double nrz = B * rx - A * rz;
                rx = nrx; rz = nrz;
                if (j < 7) {
                    double rx2 = C[j] * rx + SP[j] * w;
                    w = C[j] * w + SN[j] * rx;
                    rx = rx2;
                }
            }
            if (m == 0) hv[t] = rz;
            else        gv[t] = rz / (s * x);
        }
    }
    __syncwarp();
    if (t < 16) {
        int k = t & 7;
        const double* src = (t < 8) ? hv : gv;
        double acc = 0.0;
#pragma unroll
        for (int j = 0; j < 8; j++)
            acc += src[j] * cos16(k * (2 * j + 1));
        acc *= ((k == 0) ? 1.0 : 2.0) / 8.0;
        if (t < 8) hc[k] = acc; else gc[k] = acc;
    }
    __syncwarp();
    if (t < 16) {
        // monomial-in-y coefficients (exact integer transform, double)
        int j = t & 7;
        const double* cs = (t < 8) ? hc : gc;
        double m = 0.0;
#pragma unroll
        for (int k = 0; k < 8; k++)
            m += cs[k] * c_T[k][j];
        float f = (float)m;
        u64 pkv = ((u64)__float_as_uint(f) << 32) | (u64)__float_as_uint(f);
        if (t < 8) g_pk[j] = pkv;
        else if (j < 7) g_pk[8 + j] = pkv;   // g has deg 6
    }
    if (t == 16) g_pk[15] = 0ULL;
}

// ---------------------- packed f32x2 helpers ----------------------
__device__ __forceinline__ u64 pk2(float lo, float hi) {
    u64 r; asm("mov.b64 %0, {%1, %2};" : "=l"(r) : "f"(lo), "f"(hi)); return r;
}
__device__ __forceinline__ void unpk2(u64 v, float& lo, float& hi) {
    asm("mov.b64 {%0, %1}, %2;" : "=f"(lo), "=f"(hi) : "l"(v));
}
__device__ __forceinline__ u64 fma2(u64 a, u64 b, u64 c) {
    u64 d; asm("fma.rn.f32x2 %0, %1, %2, %3;" : "=l"(d) : "l"(a), "l"(b), "l"(c)); return d;
}
__device__ __forceinline__ u64 mul2(u64 a, u64 b) {
    u64 d; asm("mul.rn.f32x2 %0, %1, %2;" : "=l"(d) : "l"(a), "l"(b)); return d;
}
// ---------------------- scalar MUFU ----------------------
__device__ __forceinline__ float aprx_sqrt(float x) {
    float r; asm("sqrt.approx.f32 %0, %1;" : "=f"(r) : "f"(x)); return r;
}
__device__ __forceinline__ float aprx_sin(float x) {
    float r; asm("sin.approx.f32 %0, %1;" : "=f"(r) : "f"(x)); return r;
}
__device__ __forceinline__ float aprx_cos(float x) {
    float r; asm("cos.approx.f32 %0, %1;" : "=f"(r) : "f"(x)); return r;
}

// Two elements packed; returns packed <Z>.
__device__ __forceinline__ u64 qsvt_pair(float xa, float xb,
                                         const u64* __restrict__ K,
                                         u64 TWO, u64 NEG1) {
    xa = fminf(fmaxf(xa, -1.0f), 1.0f);
    xb = fminf(fmaxf(xb, -1.0f), 1.0f);
    float ta = fmaxf(fmaf(-xa, xa, 1.0f), 0.0f);
    float tb = fmaxf(fmaf(-xb, xb, 1.0f), 0.0f);
    float sa = aprx_sqrt(ta), sb = aprx_sqrt(tb);
    float sina = aprx_sin(xa), cosa = aprx_cos(xa);
    float sinb = aprx_sin(xb), cosb = aprx_cos(xb);

    u64 X = pk2(xa, xb);
    u64 U = mul2(X, X);
    u64 Y = fma2(U, TWO, NEG1);                            // y = 2u-1
    u64 M1 = mul2(mul2(X, pk2(sa, sb)), pk2(sina, sinb));  // s*x*sin(x)
    u64 CS = pk2(cosa, cosb);

    // Horner in y: h (deg 7), coeffs K[0..7]
    u64 H = K[7];
    H = fma2(H, Y, K[6]);
    H = fma2(H, Y, K[5]);
    H = fma2(H, Y, K[4]);
    H = fma2(H, Y, K[3]);
    H = fma2(H, Y, K[2]);
    H = fma2(H, Y, K[1]);
    H = fma2(H, Y, K[0]);

    // Horner in y: g (deg 6), coeffs K[8..14]
    u64 G = K[14];
    G = fma2(G, Y, K[13]);
    G = fma2(G, Y, K[12]);
    G = fma2(G, Y, K[11]);
    G = fma2(G, Y, K[10]);
    G = fma2(G, Y, K[9]);
    G = fma2(G, Y, K[8]);

    return fma2(M1, G, mul2(CS, H));   // cos*h + s*x*sin*g
}

__global__ void __launch_bounds__(256) qsvt_main(const float* __restrict__ xin,
                                                 float* __restrict__ out,
                                                 int n) {
    u64 K[16];
    {
        const ulonglong2* p = reinterpret_cast<const ulonglong2*>(g_pk);
#pragma unroll
        for (int i = 0; i < 8; i++) { ulonglong2 v = p[i]; K[2 * i] = v.x; K[2 * i + 1] = v.y; }
    }
    const u64 TWO  = pk2(2.0f, 2.0f);
    const u64 NEG1 = pk2(-1.0f, -1.0f);

    long long tid  = (long long)blockIdx.x * blockDim.x + threadIdx.x;
    long long base = tid * 8;
    if (base >= n) return;

    if (base + 8 <= n) {
        float4 a = *reinterpret_cast<const float4*>(xin + base);
        float4 b = *reinterpret_cast<const float4*>(xin + base + 4);

        u64 r01 = qsvt_pair(a.x, a.y, K, TWO, NEG1);
        u64 r23 = qsvt_pair(a.z, a.w, K, TWO, NEG1);
        u64 r45 = qsvt_pair(b.x, b.y, K, TWO, NEG1);
        u64 r67 = qsvt_pair(b.z, b.w, K, TWO, NEG1);

        float4 o1, o2;
        unpk2(r01, o1.x, o1.y);
        unpk2(r23, o1.z, o1.w);
        unpk2(r45, o2.x, o2.y);
        unpk2(r67, o2.z, o2.w);
        *reinterpret_cast<float4*>(out + base)     = o1;
        *reinterpret_cast<float4*>(out + base + 4) = o2;
    } else {
        for (long long i = base; i < n; i++) {
            u64 r = qsvt_pair(xin[i], 0.0f, K, TWO, NEG1);
            float lo, hi;
            unpk2(r, lo, hi);
            out[i] = lo;
        }
    }
}

extern "C" void kernel_launch(void* const* d_in, const int* in_sizes, int n_in,
                              void* d_out, int out_size) {
    const float* x   = (const float*)d_in[0];
    // d_in[1] = theta: dead (diagonal phase, does not affect <Z>)
    const float* phi = (const float*)d_in[2];
    float* out = (float*)d_out;

    qsvt_setup<<<1, 32>>>(phi);

    int n = out_size;
    long long threads = ((long long)n + 7) / 8;
    int blocks = (int)((threads + 255) / 256);
    qsvt_main<<<blocks, 256>>>(x, out, n);
}